// round 15
// baseline (speedup 1.0000x reference)
#include <cuda_runtime.h>
#include <cuda_bf16.h>
#include <mma.h>
#include <cstdint>

using namespace nvcuda;

#define FULL_MASK 0xFFFFFFFFu
typedef unsigned long long ull;

// cp.async 16B (compute_80+ PTX)
#define CP_ASYNC16(dst_u32, src_ptr) \
    asm volatile("cp.async.cg.shared.global [%0], [%1], 16;" \
                 :: "r"(dst_u32), "l"(src_ptr) : "memory")
#define CP_COMMIT() asm volatile("cp.async.commit_group;" ::: "memory")
#define CP_WAIT0()  asm volatile("cp.async.wait_group 0;" ::: "memory")

__device__ __forceinline__ uint32_t smem_u32(const void* p) {
    return (uint32_t)__cvta_generic_to_shared(p);
}

// split fp32 pair -> bf16 hi pair + bf16 lo pair (packed u32 each)
__device__ __forceinline__ void split2(float v0, float v1, uint32_t& h, uint32_t& l) {
    uint32_t hh;
    asm("cvt.rn.bf16x2.f32 %0, %1, %2;" : "=r"(hh) : "f"(v1), "f"(v0));
    const float h0 = __uint_as_float(hh << 16);
    const float h1 = __uint_as_float(hh & 0xFFFF0000u);
    uint32_t ll;
    asm("cvt.rn.bf16x2.f32 %0, %1, %2;" : "=r"(ll) : "f"(v1 - h1), "f"(v0 - h0));
    h = hh; l = ll;
}

// ---------------- model constants ----------------
__constant__ int FOFF[23] = {0,4,8,12,16,20,24,28,32,36,40,44,48,50,52,53,57,58,59,60,61,62,63};
__constant__ int FDIM[23] = {4,4,4,4,4,4,4,4,4,4,4,4, 2, 2, 1, 4, 1, 1, 1, 1, 1, 1, 2};

static constexpr int OBS  = 65;
static constexpr int NF   = 23;
static constexpr int ZDIM = 230;
static constexpr int HID  = 164;
static constexpr int BATCH = 131072;
static constexpr int ZS   = 232;
static constexpr int NPB  = 200;   // B row stride bf16 (400 B = 16 mod 128: conflict-free)
static constexpr int AST  = 248;   // A row stride bf16 (496 B = 112 mod 128: conflict-free)
static constexpr int SLOT_BF = 12800;   // 25600 B per ping-pong slot (32 rows hi+lo)

__device__ __align__(16) float g_wh[6 * 168];
__device__ float g_bh[6];
__device__ __align__(16) float g_wproj[NF * 10 * 4];
__device__ __align__(16) float g_wqkv[10 * 32];
__device__ int g_offadj[32];
__device__ float g_z[(size_t)BATCH * ZS];
// bf16 hi/lo weight blobs, row-major [K_pad][NPB]; bias folded at k=K_real
__device__ __align__(16) unsigned char g_wb[755200];

__host__ __device__ __forceinline__ int wb_off(int l) {
    return (l == 0) ? 0 : 192000 + (l - 1) * 140800;
}
__host__ __device__ __forceinline__ int wb_half(int l) {
    return (l == 0) ? 96000 : 70400;
}

// ======================= pack: phase1 weights + heads ===================
__global__ void pack_misc(
    const float* __restrict__ Wm, const float* __restrict__ bm,
    const float* __restrict__ Wmk, const float* __restrict__ bmk,
    const float* __restrict__ Wp,
    const float* __restrict__ Wq, const float* __restrict__ Wk,
    const float* __restrict__ Wv)
{
    const int k = blockIdx.x;   // 0..231
    const int l = blockIdx.y;   // 0..2
    const int c = threadIdx.x;  // 0..191
    if (l == 0) {
        if (k >= 168 || c >= 6) return;
        g_wh[c * 168 + k] = (k < HID) ? ((c < 5) ? Wm[k * 5 + c] : Wmk[k]) : 0.f;
        if (k == 0) g_bh[c] = (c < 5) ? bm[c] : bmk[0];
    } else if (l == 1) {
        if (k < ZDIM && c < 4) {
            const int i = k / 10;
            const int off  = FOFF[i];
            const int dim  = FDIM[i];
            const int offa = (off < 61) ? off : 61;
            const int shift = off - offa;
            float v = 0.f;
            if (c >= shift && (c - shift) < dim) v = Wp[(offa + c) * ZDIM + k];
            g_wproj[k * 4 + c] = v;
        }
        if (c == 4 && k < 32)
            g_offadj[k] = (k < NF) ? ((FOFF[k] < 61) ? FOFF[k] : 61) : 0;
    } else {
        if (k < 10 && c < 32) {
            float v = 0.f;
            if (c < 10)      v = Wq[k * 10 + c];
            else if (c < 20) v = Wk[k * 10 + (c - 10)];
            else if (c < 30) v = Wv[k * 10 + (c - 20)];
            g_wqkv[k * 32 + c] = v;
        }
    }
}

// ======================= pack: MLP weight blobs (bf16 hi/lo) ============
__global__ void pack_wb(
    const float* __restrict__ W1, const float* __restrict__ W2,
    const float* __restrict__ W3, const float* __restrict__ W4,
    const float* __restrict__ W5,
    const float* __restrict__ b1, const float* __restrict__ b2,
    const float* __restrict__ b3, const float* __restrict__ b4,
    const float* __restrict__ b5)
{
    const int k = blockIdx.x;          // 0..239
    const int l = blockIdx.y >> 1;     // 0..4
    const int h = blockIdx.y & 1;      // 0 hi, 1 lo
    const int n = threadIdx.x;         // 0..199
    const int kalloc = (l == 0) ? 240 : 176;
    if (k >= kalloc) return;
    const int kreal = (l == 0) ? 230 : 164;
    const float* W = (l == 0) ? W1 : (l == 1) ? W2 : (l == 2) ? W3 : (l == 3) ? W4 : W5;
    const float* b = (l == 0) ? b1 : (l == 1) ? b2 : (l == 2) ? b3 : (l == 3) ? b4 : b5;
    float w = 0.f;
    if (n < HID) {
        if (k < kreal)       w = W[k * HID + n];
        else if (k == kreal) w = b[n];
    }
    const __nv_bfloat16 bhi = __float2bfloat16(w);
    unsigned short bits;
    if (h == 0) bits = __bfloat16_as_ushort(bhi);
    else        bits = __bfloat16_as_ushort(__float2bfloat16(w - __bfloat162float(bhi)));
    *(unsigned short*)(g_wb + wb_off(l) + h * wb_half(l) + (k * NPB + n) * 2) = bits;
}

// ======================= Phase 1: proj + attention (unchanged) ==========
__global__ void __launch_bounds__(256, 2)
phase1_kernel(const float* __restrict__ x, const float* __restrict__ bpj, int B)
{
    __shared__ float kvs[8][1152];
    const int tid  = threadIdx.x;
    const int w    = tid >> 5;
    const int lane = tid & 31;
    float* kb0 = kvs[w];
    float* vb0 = kvs[w] + 288;
    float* kb1 = kvs[w] + 576;
    float* vb1 = kvs[w] + 864;

    const float inv_sqrt10 = 0.31622776601683794f;
    const int tok = (lane < NF) ? lane : 0;
    const int offa = g_offadj[tok];
    float bq[10];
    {
        const float2* b2 = (const float2*)(bpj + tok * 10);
        #pragma unroll
        for (int u = 0; u < 5; u++) { float2 t = b2[u]; bq[2*u] = t.x; bq[2*u+1] = t.y; }
    }
    const int rowbase = blockIdx.x * 32 + w * 4;

    #pragma unroll 1
    for (int pass = 0; pass < 2; pass++) {
        const int row0 = rowbase + 2 * pass;
        const int row1 = row0 + 1;
        float* zrow0 = g_z + (size_t)row0 * ZS;
        float* zrow1 = g_z + (size_t)row1 * ZS;
        const float* xr0 = x + (long long)row0 * OBS + offa;
        const float* xr1 = x + (long long)row1 * OBS + offa;
        const float x00 = xr0[0], x01 = xr0[1], x02 = xr0[2], x03 = xr0[3];
        const float x10 = xr1[0], x11 = xr1[1], x12 = xr1[2], x13 = xr1[3];

        float h0[10], h1[10];
        #pragma unroll
        for (int e = 0; e < 10; e++) {
            const float4 wq = ((const float4*)g_wproj)[tok * 10 + e];
            h0[e] = fmaf(x03, wq.w, fmaf(x02, wq.z, fmaf(x01, wq.y, fmaf(x00, wq.x, bq[e]))));
            h1[e] = fmaf(x13, wq.w, fmaf(x12, wq.z, fmaf(x11, wq.y, fmaf(x10, wq.x, bq[e]))));
        }
        {
            float kk0[10], vv0[10], kk1[10], vv1[10];
            #pragma unroll
            for (int e = 0; e < 10; e++) { kk0[e]=0.f; vv0[e]=0.f; kk1[e]=0.f; vv1[e]=0.f; }
            #pragma unroll
            for (int d = 0; d < 10; d++) {
                float wf[24];
                #pragma unroll
                for (int u = 0; u < 6; u++)
                    *(float4*)(wf + 4 * u) = ((const float4*)(g_wqkv + d * 32))[2 + u];
                const float hd0 = h0[d], hd1 = h1[d];
                #pragma unroll
                for (int e = 0; e < 10; e++) {
                    kk0[e] = fmaf(hd0, wf[e + 2],  kk0[e]);
                    kk1[e] = fmaf(hd1, wf[e + 2],  kk1[e]);
                    vv0[e] = fmaf(hd0, wf[e + 12], vv0[e]);
                    vv1[e] = fmaf(hd1, wf[e + 12], vv1[e]);
                }
            }
            if (lane < NF) {
                float2* ks0 = (float2*)(kb0 + tok * 12);
                float2* vs0 = (float2*)(vb0 + tok * 12);
                float2* ks1 = (float2*)(kb1 + tok * 12);
                float2* vs1 = (float2*)(vb1 + tok * 12);
                #pragma unroll
                for (int u = 0; u < 5; u++) {
                    ks0[u] = make_float2(kk0[2*u], kk0[2*u+1]);
                    vs0[u] = make_float2(vv0[2*u], vv0[2*u+1]);
                    ks1[u] = make_float2(kk1[2*u], kk1[2*u+1]);
                    vs1[u] = make_float2(vv1[2*u], vv1[2*u+1]);
                }
            }
        }
        float q0[10], q1[10];
        #pragma unroll
        for (int e = 0; e < 10; e++) { q0[e] = 0.f; q1[e] = 0.f; }
        #pragma unroll
        for (int d = 0; d < 10; d++) {
            float wf[12];
            #pragma unroll
            for (int u = 0; u < 3; u++)
                *(float4*)(wf + 4 * u) = ((const float4*)(g_wqkv + d * 32))[u];
            const float hd0 = h0[d], hd1 = h1[d];
            #pragma unroll
            for (int e = 0; e < 10; e++) {
                q0[e] = fmaf(hd0, wf[e], q0[e]);
                q1[e] = fmaf(hd1, wf[e], q1[e]);
            }
        }
        __syncwarp();

        float ssum0 = 0.f, ssum1 = 0.f;
        float ctx0[10], ctx1[10];
        #pragma unroll
        for (int e = 0; e < 10; e++) { ctx0[e] = 0.f; ctx1[e] = 0.f; }
        #pragma unroll 1
        for (int j = 0; j < NF; j++) {
            const float* kj0 = kb0 + j * 12;
            const float4 ka0 = *(const float4*)kj0;
            const float4 kb0v = *(const float4*)(kj0 + 4);
            const float2 kc0 = *(const float2*)(kj0 + 8);
            const float* kj1 = kb1 + j * 12;
            const float4 ka1 = *(const float4*)kj1;
            const float4 kb1v = *(const float4*)(kj1 + 4);
            const float2 kc1 = *(const float2*)(kj1 + 8);
            float dt0 = q0[0] * ka0.x;
            float dt1 = q1[0] * ka1.x;
            dt0 = fmaf(q0[1], ka0.y, dt0);  dt1 = fmaf(q1[1], ka1.y, dt1);
            dt0 = fmaf(q0[2], ka0.z, dt0);  dt1 = fmaf(q1[2], ka1.z, dt1);
            dt0 = fmaf(q0[3], ka0.w, dt0);  dt1 = fmaf(q1[3], ka1.w, dt1);
            dt0 = fmaf(q0[4], kb0v.x, dt0); dt1 = fmaf(q1[4], kb1v.x, dt1);
            dt0 = fmaf(q0[5], kb0v.y, dt0); dt1 = fmaf(q1[5], kb1v.y, dt1);
            dt0 = fmaf(q0[6], kb0v.z, dt0); dt1 = fmaf(q1[6], kb1v.z, dt1);
            dt0 = fmaf(q0[7], kb0v.w, dt0); dt1 = fmaf(q1[7], kb1v.w, dt1);
            dt0 = fmaf(q0[8], kc0.x, dt0);  dt1 = fmaf(q1[8], kc1.x, dt1);
            dt0 = fmaf(q0[9], kc0.y, dt0);  dt1 = fmaf(q1[9], kc1.y, dt1);
            const float pe0 = __expf(dt0 * inv_sqrt10);
            const float pe1 = __expf(dt1 * inv_sqrt10);
            ssum0 += pe0;
            ssum1 += pe1;
            const float* vj0 = vb0 + j * 12;
            const float4 va0 = *(const float4*)vj0;
            const float4 vb0v = *(const float4*)(vj0 + 4);
            const float2 vc0 = *(const float2*)(vj0 + 8);
            const float* vj1 = vb1 + j * 12;
            const float4 va1 = *(const float4*)vj1;
            const float4 vb1v = *(const float4*)(vj1 + 4);
            const float2 vc1 = *(const float2*)(vj1 + 8);
            ctx0[0] = fmaf(pe0, va0.x, ctx0[0]);  ctx1[0] = fmaf(pe1, va1.x, ctx1[0]);
            ctx0[1] = fmaf(pe0, va0.y, ctx0[1]);  ctx1[1] = fmaf(pe1, va1.y, ctx1[1]);
            ctx0[2] = fmaf(pe0, va0.z, ctx0[2]);  ctx1[2] = fmaf(pe1, va1.z, ctx1[2]);
            ctx0[3] = fmaf(pe0, va0.w, ctx0[3]);  ctx1[3] = fmaf(pe1, va1.w, ctx1[3]);
            ctx0[4] = fmaf(pe0, vb0v.x, ctx0[4]); ctx1[4] = fmaf(pe1, vb1v.x, ctx1[4]);
            ctx0[5] = fmaf(pe0, vb0v.y, ctx0[5]); ctx1[5] = fmaf(pe1, vb1v.y, ctx1[5]);
            ctx0[6] = fmaf(pe0, vb0v.z, ctx0[6]); ctx1[6] = fmaf(pe1, vb1v.z, ctx1[6]);
            ctx0[7] = fmaf(pe0, vb0v.w, ctx0[7]); ctx1[7] = fmaf(pe1, vb1v.w, ctx1[7]);
            ctx0[8] = fmaf(pe0, vc0.x, ctx0[8]);  ctx1[8] = fmaf(pe1, vc1.x, ctx1[8]);
            ctx0[9] = fmaf(pe0, vc0.y, ctx0[9]);  ctx1[9] = fmaf(pe1, vc1.y, ctx1[9]);
        }
        const float rs0 = __fdividef(1.f, ssum0);
        const float rs1 = __fdividef(1.f, ssum1);
        if (lane < NF) {
            float2* zs0 = (float2*)(zrow0 + tok * 10);
            float2* zs1 = (float2*)(zrow1 + tok * 10);
            #pragma unroll
            for (int u = 0; u < 5; u++) {
                zs0[u] = make_float2(fmaf(ctx0[2*u],   rs0, h0[2*u]),
                                     fmaf(ctx0[2*u+1], rs0, h0[2*u+1]));
                zs1[u] = make_float2(fmaf(ctx1[2*u],   rs1, h1[2*u]),
                                     fmaf(ctx1[2*u+1], rs1, h1[2*u+1]));
            }
        }
        if (lane == NF) {
            zrow0[230] = 0.f; zrow0[231] = 0.f;
            zrow1[230] = 0.f; zrow1[231] = 0.f;
        }
        __syncwarp();
    }
}

// ======================= Phase 2: wmma bf16 MLP + heads =================
// M=64/CTA, 128 threads (4 warps), occ 2, reg cap 255.
// Warp tile 4m x 3n: B loads amortized over all 4 m-tiles.
// smem: Ah [64][248] (31744 B) | Al (31744 B) | Bs 2 slots x 25600 B
static constexpr int AHI = 0;
static constexpr int ALO = 31744;
static constexpr int BBO = 63488;
static constexpr int SMEM2 = 63488 + 51200;   // 114688 B

__global__ void __launch_bounds__(128, 2)
phase2_wmma(float* __restrict__ out, int B)
{
    extern __shared__ char smp[];
    __nv_bfloat16* Ah = (__nv_bfloat16*)(smp + AHI);
    __nv_bfloat16* Al = (__nv_bfloat16*)(smp + ALO);
    __nv_bfloat16* Bs = (__nv_bfloat16*)(smp + BBO);
    const uint32_t bs_u32 = smem_u32(Bs);
    const int tid  = threadIdx.x;
    const int w    = tid >> 5;         // 0..3 = n-group: n-tiles {w*3..w*3+2}
    const int lane = tid & 31;
    const int rowbase = blockIdx.x * 64;

    // cooperative async copy of one B chunk (hi+lo) into a slot
    auto issue_copy = [&](int loff, int half, int k0, int klen, int slot) {
        const unsigned char* sh = g_wb + loff + k0 * (NPB * 2);
        const unsigned char* sl = g_wb + loff + half + k0 * (NPB * 2);
        const uint32_t dst = bs_u32 + slot * (SLOT_BF * 2);
        const uint32_t dlo = dst + klen * (NPB * 2);
        const int cnt = klen * 25;        // klen*400/16
        for (int i = tid; i < cnt; i += 128) {
            CP_ASYNC16(dst + i * 16, sh + i * 16);
            CP_ASYNC16(dlo + i * 16, sl + i * 16);
        }
        CP_COMMIT();
    };

    // prefetch layer-0 chunk 0 (overlaps A init)
    issue_copy(wb_off(0), wb_half(0), 0, 32, 0);

    // ---- A init from g_z: bias-one at k=230, zeros to 239 ----
    #pragma unroll 1
    for (int i = tid; i < 64 * 120; i += 128) {
        const int m  = i / 120;
        const int k0 = (i - m * 120) * 2;
        const float* zr = g_z + (size_t)(rowbase + m) * ZS;
        const float v0 = (k0 < 230) ? zr[k0] : ((k0 == 230) ? 1.f : 0.f);
        const float v1 = (k0 + 1 < 230) ? zr[k0 + 1] : 0.f;
        uint32_t h, l;
        split2(v0, v1, h, l);
        *(uint32_t*)(Ah + m * AST + k0) = h;
        *(uint32_t*)(Al + m * AST + k0) = l;
    }

    int cur = 0;
    #pragma unroll 1
    for (int l = 0; l < 5; l++) {
        const int KP = (l == 0) ? 240 : 176;
        const int nc = (KP + 31) >> 5;          // 8 or 6 chunks
        wmma::fragment<wmma::accumulator, 16, 16, 16, float> acc[4][3];
        #pragma unroll
        for (int i = 0; i < 4; i++)
            #pragma unroll
            for (int j = 0; j < 3; j++) wmma::fill_fragment(acc[i][j], 0.f);

        #pragma unroll 1
        for (int c = 0; c < nc; c++) {
            const int k0 = c * 32;
            const int klen = (KP - k0 < 32) ? (KP - k0) : 32;
            CP_WAIT0();
            __syncthreads();      // chunk c ready; all warps done with slot cur^1
            if (c + 1 < nc) {
                const int nk0 = k0 + 32;
                issue_copy(wb_off(l), wb_half(l), nk0,
                           (KP - nk0 < 32) ? (KP - nk0) : 32, cur ^ 1);
            } else if (l < 4) {
                issue_copy(wb_off(l + 1), wb_half(l + 1), 0, 32, cur ^ 1);
            }
            const __nv_bfloat16* Bslot = Bs + cur * SLOT_BF;
            const int nks = klen >> 4;
            #pragma unroll 1
            for (int ks = 0; ks < nks; ks++) {
                wmma::fragment<wmma::matrix_a, 16, 16, 16, __nv_bfloat16, wmma::row_major> fah[4], fal[4];
                #pragma unroll
                for (int i = 0; i < 4; i++) {
                    const int mbase = i * 16 * AST + k0 + ks * 16;
                    wmma::load_matrix_sync(fah[i], Ah + mbase, AST);
                    wmma::load_matrix_sync(fal[i], Al + mbase, AST);
                }
                #pragma unroll
                for (int j = 0; j < 3; j++) {
                    const int nbase = ks * 16 * NPB + (w * 3 + j) * 16;
                    wmma::fragment<wmma::matrix_b, 16, 16, 16, __nv_bfloat16, wmma::row_major> fbh, fbl;
                    wmma::load_matrix_sync(fbh, Bslot + nbase, NPB);
                    wmma::load_matrix_sync(fbl, Bslot + klen * NPB + nbase, NPB);
                    #pragma unroll
                    for (int i = 0; i < 4; i++) {
                        wmma::mma_sync(acc[i][j], fah[i], fbh, acc[i][j]);
                        wmma::mma_sync(acc[i][j], fal[i], fbh, acc[i][j]);
                        wmma::mma_sync(acc[i][j], fah[i], fbl, acc[i][j]);
                    }
                }
            }
            cur ^= 1;
        }
        __syncthreads();   // all warps done with last compute slot (cur^1)

        // ---- epilogue: staging in the dead slot (cur^1) ----
        float* stg = (float*)(Bs + (cur ^ 1) * SLOT_BF) + w * 260;
        const int r  = lane >> 1;
        const int c0 = (lane & 1) * 8;
        if (l < 4) {
            #pragma unroll 1
            for (int i = 0; i < 4; i++) {
                #pragma unroll 1
                for (int j = 0; j < 3; j++) {
                    wmma::store_matrix_sync(stg, acc[i][j], 16, wmma::mem_row_major);
                    __syncwarp();
                    const int ncol = (w * 3 + j) * 16 + c0;
                    float v[8];
                    #pragma unroll
                    for (int jj = 0; jj < 8; jj++) {
                        const int k = ncol + jj;
                        const float xv = stg[r * 16 + c0 + jj];
                        v[jj] = (k < 164) ? fmaxf(xv, 0.f) : ((k == 164) ? 1.f : 0.f);
                    }
                    uint32_t hh[4], ll[4];
                    #pragma unroll
                    for (int p = 0; p < 4; p++) split2(v[2*p], v[2*p+1], hh[p], ll[p]);
                    const int m = i * 16 + r;
                    *(uint4*)(Ah + m * AST + ncol) = make_uint4(hh[0], hh[1], hh[2], hh[3]);
                    *(uint4*)(Al + m * AST + ncol) = make_uint4(ll[0], ll[1], ll[2], ll[3]);
                    __syncwarp();
                }
            }
        } else {
            // final layer: fp32 ReLU z into A region (za [64][168])
            float* za = (float*)smp;
            #pragma unroll 1
            for (int i = 0; i < 4; i++) {
                #pragma unroll 1
                for (int j = 0; j < 3; j++) {
                    wmma::store_matrix_sync(stg, acc[i][j], 16, wmma::mem_row_major);
                    __syncwarp();
                    const int ncol = (w * 3 + j) * 16 + c0;
                    const int m = i * 16 + r;
                    #pragma unroll
                    for (int jj = 0; jj < 8; jj++) {
                        const int k = ncol + jj;
                        if (k < 164)
                            za[m * 168 + k] = fmaxf(stg[r * 16 + c0 + jj], 0.f);
                    }
                    __syncwarp();
                }
            }
        }
        __syncthreads();
    }

    // ---- heads: move[5] + mark[1], fp32 ----
    {
        float* za  = (float*)smp;
        float* whs = (float*)Bs;    // [k][6]
        for (int i = tid; i < 1008; i += 128) {
            const int o = i / 168, k = i - o * 168;
            whs[k * 6 + o] = g_wh[i];
        }
        __syncthreads();
        const int r = tid >> 1;     // 0..63
        const int g = tid & 1;
        const float* zr = za + r * 168;
        float a0 = g_bh[g * 3 + 0];
        float a1 = g_bh[g * 3 + 1];
        float a2 = g_bh[g * 3 + 2];
        #pragma unroll 4
        for (int k = 0; k < 164; k++) {
            const float v = zr[k];
            const float* wk = whs + k * 6 + g * 3;
            a0 = fmaf(v, wk[0], a0);
            a1 = fmaf(v, wk[1], a1);
            a2 = fmaf(v, wk[2], a2);
        }
        const int row = rowbase + r;
        if (g == 0) {
            out[row * 5 + 0] = a0;
            out[row * 5 + 1] = a1;
            out[row * 5 + 2] = a2;
        } else {
            out[row * 5 + 3] = a0;
            out[row * 5 + 4] = a1;
            out[(long long)B * 5 + row] = a2;
        }
    }
}

extern "C" void kernel_launch(void* const* d_in, const int* in_sizes, int n_in,
                              void* d_out, int out_size) {
    const float* x   = (const float*)d_in[0];
    const float* Wp  = (const float*)d_in[1];
    const float* bp  = (const float*)d_in[2];
    const float* Wq  = (const float*)d_in[3];
    const float* Wk  = (const float*)d_in[4];
    const float* Wv  = (const float*)d_in[5];
    const float* W1  = (const float*)d_in[6];
    const float* b1  = (const float*)d_in[7];
    const float* W2  = (const float*)d_in[8];
    const float* b2  = (const float*)d_in[9];
    const float* W3  = (const float*)d_in[10];
    const float* b3  = (const float*)d_in[11];
    const float* W4  = (const float*)d_in[12];
    const float* b4  = (const float*)d_in[13];
    const float* W5  = (const float*)d_in[14];
    const float* b5  = (const float*)d_in[15];
    const float* Wm  = (const float*)d_in[16];
    const float* bm  = (const float*)d_in[17];
    const float* Wmk = (const float*)d_in[18];
    const float* bmk = (const float*)d_in[19];
    float* out = (float*)d_out;

    const int B = in_sizes[0] / OBS;

    cudaFuncSetAttribute(phase2_wmma,
                         cudaFuncAttributeMaxDynamicSharedMemorySize, SMEM2);

    pack_misc<<<dim3(232, 3), 192>>>(Wm, bm, Wmk, bmk, Wp, Wq, Wk, Wv);
    pack_wb<<<dim3(240, 10), 200>>>(W1, W2, W3, W4, W5, b1, b2, b3, b4, b5);
    phase1_kernel<<<B / 32, 256>>>(x, bp, B);
    phase2_wmma<<<B / 64, 128, SMEM2>>>(out, B);
}

// round 16
// speedup vs baseline: 1.5190x; 1.5190x over previous
#include <cuda_runtime.h>
#include <cuda_bf16.h>
#include <mma.h>
#include <cstdint>

using namespace nvcuda;

#define FULL_MASK 0xFFFFFFFFu
typedef unsigned long long ull;

// cp.async 16B (compute_80+ PTX)
#define CP_ASYNC16(dst_u32, src_ptr) \
    asm volatile("cp.async.cg.shared.global [%0], [%1], 16;" \
                 :: "r"(dst_u32), "l"(src_ptr) : "memory")
#define CP_COMMIT() asm volatile("cp.async.commit_group;" ::: "memory")
#define CP_WAIT0()  asm volatile("cp.async.wait_group 0;" ::: "memory")

__device__ __forceinline__ uint32_t smem_u32(const void* p) {
    return (uint32_t)__cvta_generic_to_shared(p);
}

// split fp32 pair -> bf16 hi pair + bf16 lo pair (packed u32 each)
__device__ __forceinline__ void split2(float v0, float v1, uint32_t& h, uint32_t& l) {
    uint32_t hh;
    asm("cvt.rn.bf16x2.f32 %0, %1, %2;" : "=r"(hh) : "f"(v1), "f"(v0));
    const float h0 = __uint_as_float(hh << 16);
    const float h1 = __uint_as_float(hh & 0xFFFF0000u);
    uint32_t ll;
    asm("cvt.rn.bf16x2.f32 %0, %1, %2;" : "=r"(ll) : "f"(v1 - h1), "f"(v0 - h0));
    h = hh; l = ll;
}

// ---------------- model constants ----------------
__constant__ int FOFF[23] = {0,4,8,12,16,20,24,28,32,36,40,44,48,50,52,53,57,58,59,60,61,62,63};
__constant__ int FDIM[23] = {4,4,4,4,4,4,4,4,4,4,4,4, 2, 2, 1, 4, 1, 1, 1, 1, 1, 1, 2};

static constexpr int OBS  = 65;
static constexpr int NF   = 23;
static constexpr int ZDIM = 230;
static constexpr int HID  = 164;
static constexpr int NPB  = 200;   // B row stride bf16 (400 B = 16 mod 128: conflict-free)
static constexpr int AST  = 248;   // A row stride bf16 (496 B = 112 mod 128: conflict-free)
static constexpr int SLOT_BF = 12800;   // 25600 B per ping-pong slot

__device__ __align__(16) float g_wh[6 * 168];
__device__ float g_bh[6];
__device__ __align__(16) float g_wproj[NF * 10 * 4];
__device__ __align__(16) float g_wqkv[10 * 32];
__device__ int g_offadj[32];
// bf16 hi/lo weight blobs, row-major [K_pad][NPB]; bias folded at k=K_real
__device__ __align__(16) unsigned char g_wb[755200];

__host__ __device__ __forceinline__ int wb_off(int l) {
    return (l == 0) ? 0 : 192000 + (l - 1) * 140800;
}
__host__ __device__ __forceinline__ int wb_half(int l) {
    return (l == 0) ? 96000 : 70400;
}

// ======================= pack: phase1 weights + heads ===================
__global__ void pack_misc(
    const float* __restrict__ Wm, const float* __restrict__ bm,
    const float* __restrict__ Wmk, const float* __restrict__ bmk,
    const float* __restrict__ Wp,
    const float* __restrict__ Wq, const float* __restrict__ Wk,
    const float* __restrict__ Wv)
{
    const int k = blockIdx.x;
    const int l = blockIdx.y;
    const int c = threadIdx.x;
    if (l == 0) {
        if (k >= 168 || c >= 6) return;
        g_wh[c * 168 + k] = (k < HID) ? ((c < 5) ? Wm[k * 5 + c] : Wmk[k]) : 0.f;
        if (k == 0) g_bh[c] = (c < 5) ? bm[c] : bmk[0];
    } else if (l == 1) {
        if (k < ZDIM && c < 4) {
            const int i = k / 10;
            const int off  = FOFF[i];
            const int dim  = FDIM[i];
            const int offa = (off < 61) ? off : 61;
            const int shift = off - offa;
            float v = 0.f;
            if (c >= shift && (c - shift) < dim) v = Wp[(offa + c) * ZDIM + k];
            g_wproj[k * 4 + c] = v;
        }
        if (c == 4 && k < 32)
            g_offadj[k] = (k < NF) ? ((FOFF[k] < 61) ? FOFF[k] : 61) : 0;
    } else {
        if (k < 10 && c < 32) {
            float v = 0.f;
            if (c < 10)      v = Wq[k * 10 + c];
            else if (c < 20) v = Wk[k * 10 + (c - 10)];
            else if (c < 30) v = Wv[k * 10 + (c - 20)];
            g_wqkv[k * 32 + c] = v;
        }
    }
}

// ======================= pack: MLP weight blobs (bf16 hi/lo) ============
__global__ void pack_wb(
    const float* __restrict__ W1, const float* __restrict__ W2,
    const float* __restrict__ W3, const float* __restrict__ W4,
    const float* __restrict__ W5,
    const float* __restrict__ b1, const float* __restrict__ b2,
    const float* __restrict__ b3, const float* __restrict__ b4,
    const float* __restrict__ b5)
{
    const int k = blockIdx.x;
    const int l = blockIdx.y >> 1;
    const int h = blockIdx.y & 1;
    const int n = threadIdx.x;
    const int kalloc = (l == 0) ? 240 : 176;
    if (k >= kalloc) return;
    const int kreal = (l == 0) ? 230 : 164;
    const float* W = (l == 0) ? W1 : (l == 1) ? W2 : (l == 2) ? W3 : (l == 3) ? W4 : W5;
    const float* b = (l == 0) ? b1 : (l == 1) ? b2 : (l == 2) ? b3 : (l == 3) ? b4 : b5;
    float w = 0.f;
    if (n < HID) {
        if (k < kreal)       w = W[k * HID + n];
        else if (k == kreal) w = b[n];
    }
    const __nv_bfloat16 bhi = __float2bfloat16(w);
    unsigned short bits;
    if (h == 0) bits = __bfloat16_as_ushort(bhi);
    else        bits = __bfloat16_as_ushort(__float2bfloat16(w - __bfloat162float(bhi)));
    *(unsigned short*)(g_wb + wb_off(l) + h * wb_half(l) + (k * NPB + n) * 2) = bits;
}

// ======================= Fused kernel: proj+attn -> wmma MLP -> heads ===
// M=64/CTA, 256 threads, occ 2.
// smem: Ah [64][248] bf16 (31744 B) | Al (31744 B) | Bs 2 slots x 25600 B
// phase-1 kv scratch overlays Bs (per warp 1152 floats, 8 warps = 36864 B).
static constexpr int AHI = 0;
static constexpr int ALO = 31744;
static constexpr int BBO = 63488;
static constexpr int SMEM2 = 63488 + 51200;   // 114688 B

__global__ void __launch_bounds__(256, 2)
actor_fused(const float* __restrict__ x, const float* __restrict__ bpj,
            float* __restrict__ out, int B)
{
    extern __shared__ char smp[];
    __nv_bfloat16* Ah = (__nv_bfloat16*)(smp + AHI);
    __nv_bfloat16* Al = (__nv_bfloat16*)(smp + ALO);
    __nv_bfloat16* Bs = (__nv_bfloat16*)(smp + BBO);
    const uint32_t bs_u32 = smem_u32(Bs);
    const int tid  = threadIdx.x;
    const int w    = tid >> 5;
    const int lane = tid & 31;
    const int rowbase = blockIdx.x * 64;

    // ================= Phase 1: proj + attention (8 rows/warp) ==========
    {
        float* kvw = (float*)(smp + BBO) + w * 1152;
        float* kb0 = kvw;
        float* vb0 = kvw + 288;
        float* kb1 = kvw + 576;
        float* vb1 = kvw + 864;

        const float inv_sqrt10 = 0.31622776601683794f;
        const int tok = (lane < NF) ? lane : 0;
        const int offa = g_offadj[tok];
        float bq[10];
        {
            const float2* b2 = (const float2*)(bpj + tok * 10);
            #pragma unroll
            for (int u = 0; u < 5; u++) { float2 t = b2[u]; bq[2*u] = t.x; bq[2*u+1] = t.y; }
        }

        #pragma unroll 1
        for (int pass = 0; pass < 4; pass++) {
            const int lr0 = w * 8 + 2 * pass;    // local row in [0,64)
            const int row0 = rowbase + lr0;
            const int row1 = row0 + 1;
            const float* xr0 = x + (long long)row0 * OBS + offa;
            const float* xr1 = x + (long long)row1 * OBS + offa;
            const float x00 = xr0[0], x01 = xr0[1], x02 = xr0[2], x03 = xr0[3];
            const float x10 = xr1[0], x11 = xr1[1], x12 = xr1[2], x13 = xr1[3];

            float h0[10], h1[10];
            #pragma unroll
            for (int e = 0; e < 10; e++) {
                const float4 wq = ((const float4*)g_wproj)[tok * 10 + e];
                h0[e] = fmaf(x03, wq.w, fmaf(x02, wq.z, fmaf(x01, wq.y, fmaf(x00, wq.x, bq[e]))));
                h1[e] = fmaf(x13, wq.w, fmaf(x12, wq.z, fmaf(x11, wq.y, fmaf(x10, wq.x, bq[e]))));
            }
            {
                float kk0[10], vv0[10], kk1[10], vv1[10];
                #pragma unroll
                for (int e = 0; e < 10; e++) { kk0[e]=0.f; vv0[e]=0.f; kk1[e]=0.f; vv1[e]=0.f; }
                #pragma unroll
                for (int d = 0; d < 10; d++) {
                    float wf[24];
                    #pragma unroll
                    for (int u = 0; u < 6; u++)
                        *(float4*)(wf + 4 * u) = ((const float4*)(g_wqkv + d * 32))[2 + u];
                    const float hd0 = h0[d], hd1 = h1[d];
                    #pragma unroll
                    for (int e = 0; e < 10; e++) {
                        kk0[e] = fmaf(hd0, wf[e + 2],  kk0[e]);
                        kk1[e] = fmaf(hd1, wf[e + 2],  kk1[e]);
                        vv0[e] = fmaf(hd0, wf[e + 12], vv0[e]);
                        vv1[e] = fmaf(hd1, wf[e + 12], vv1[e]);
                    }
                }
                if (lane < NF) {
                    float2* ks0 = (float2*)(kb0 + tok * 12);
                    float2* vs0 = (float2*)(vb0 + tok * 12);
                    float2* ks1 = (float2*)(kb1 + tok * 12);
                    float2* vs1 = (float2*)(vb1 + tok * 12);
                    #pragma unroll
                    for (int u = 0; u < 5; u++) {
                        ks0[u] = make_float2(kk0[2*u], kk0[2*u+1]);
                        vs0[u] = make_float2(vv0[2*u], vv0[2*u+1]);
                        ks1[u] = make_float2(kk1[2*u], kk1[2*u+1]);
                        vs1[u] = make_float2(vv1[2*u], vv1[2*u+1]);
                    }
                }
            }
            float q0[10], q1[10];
            #pragma unroll
            for (int e = 0; e < 10; e++) { q0[e] = 0.f; q1[e] = 0.f; }
            #pragma unroll
            for (int d = 0; d < 10; d++) {
                float wf[12];
                #pragma unroll
                for (int u = 0; u < 3; u++)
                    *(float4*)(wf + 4 * u) = ((const float4*)(g_wqkv + d * 32))[u];
                const float hd0 = h0[d], hd1 = h1[d];
                #pragma unroll
                for (int e = 0; e < 10; e++) {
                    q0[e] = fmaf(hd0, wf[e], q0[e]);
                    q1[e] = fmaf(hd1, wf[e], q1[e]);
                }
            }
            __syncwarp();

            float ssum0 = 0.f, ssum1 = 0.f;
            float ctx0[10], ctx1[10];
            #pragma unroll
            for (int e = 0; e < 10; e++) { ctx0[e] = 0.f; ctx1[e] = 0.f; }
            #pragma unroll 1
            for (int j = 0; j < NF; j++) {
                const float* kj0 = kb0 + j * 12;
                const float4 ka0 = *(const float4*)kj0;
                const float4 kb0v = *(const float4*)(kj0 + 4);
                const float2 kc0 = *(const float2*)(kj0 + 8);
                const float* kj1 = kb1 + j * 12;
                const float4 ka1 = *(const float4*)kj1;
                const float4 kb1v = *(const float4*)(kj1 + 4);
                const float2 kc1 = *(const float2*)(kj1 + 8);
                float dt0 = q0[0] * ka0.x;
                float dt1 = q1[0] * ka1.x;
                dt0 = fmaf(q0[1], ka0.y, dt0);  dt1 = fmaf(q1[1], ka1.y, dt1);
                dt0 = fmaf(q0[2], ka0.z, dt0);  dt1 = fmaf(q1[2], ka1.z, dt1);
                dt0 = fmaf(q0[3], ka0.w, dt0);  dt1 = fmaf(q1[3], ka1.w, dt1);
                dt0 = fmaf(q0[4], kb0v.x, dt0); dt1 = fmaf(q1[4], kb1v.x, dt1);
                dt0 = fmaf(q0[5], kb0v.y, dt0); dt1 = fmaf(q1[5], kb1v.y, dt1);
                dt0 = fmaf(q0[6], kb0v.z, dt0); dt1 = fmaf(q1[6], kb1v.z, dt1);
                dt0 = fmaf(q0[7], kb0v.w, dt0); dt1 = fmaf(q1[7], kb1v.w, dt1);
                dt0 = fmaf(q0[8], kc0.x, dt0);  dt1 = fmaf(q1[8], kc1.x, dt1);
                dt0 = fmaf(q0[9], kc0.y, dt0);  dt1 = fmaf(q1[9], kc1.y, dt1);
                const float pe0 = __expf(dt0 * inv_sqrt10);
                const float pe1 = __expf(dt1 * inv_sqrt10);
                ssum0 += pe0;
                ssum1 += pe1;
                const float* vj0 = vb0 + j * 12;
                const float4 va0 = *(const float4*)vj0;
                const float4 vb0v = *(const float4*)(vj0 + 4);
                const float2 vc0 = *(const float2*)(vj0 + 8);
                const float* vj1 = vb1 + j * 12;
                const float4 va1 = *(const float4*)vj1;
                const float4 vb1v = *(const float4*)(vj1 + 4);
                const float2 vc1 = *(const float2*)(vj1 + 8);
                ctx0[0] = fmaf(pe0, va0.x, ctx0[0]);  ctx1[0] = fmaf(pe1, va1.x, ctx1[0]);
                ctx0[1] = fmaf(pe0, va0.y, ctx0[1]);  ctx1[1] = fmaf(pe1, va1.y, ctx1[1]);
                ctx0[2] = fmaf(pe0, va0.z, ctx0[2]);  ctx1[2] = fmaf(pe1, va1.z, ctx1[2]);
                ctx0[3] = fmaf(pe0, va0.w, ctx0[3]);  ctx1[3] = fmaf(pe1, va1.w, ctx1[3]);
                ctx0[4] = fmaf(pe0, vb0v.x, ctx0[4]); ctx1[4] = fmaf(pe1, vb1v.x, ctx1[4]);
                ctx0[5] = fmaf(pe0, vb0v.y, ctx0[5]); ctx1[5] = fmaf(pe1, vb1v.y, ctx1[5]);
                ctx0[6] = fmaf(pe0, vb0v.z, ctx0[6]); ctx1[6] = fmaf(pe1, vb1v.z, ctx1[6]);
                ctx0[7] = fmaf(pe0, vb0v.w, ctx0[7]); ctx1[7] = fmaf(pe1, vb1v.w, ctx1[7]);
                ctx0[8] = fmaf(pe0, vc0.x, ctx0[8]);  ctx1[8] = fmaf(pe1, vc1.x, ctx1[8]);
                ctx0[9] = fmaf(pe0, vc0.y, ctx0[9]);  ctx1[9] = fmaf(pe1, vc1.y, ctx1[9]);
            }
            const float rs0 = __fdividef(1.f, ssum0);
            const float rs1 = __fdividef(1.f, ssum1);
            // z = h + ctx*rs -> split to bf16 hi/lo directly into Ah/Al
            if (lane < NF) {
                #pragma unroll
                for (int u = 0; u < 5; u++) {
                    const int col = tok * 10 + 2 * u;
                    float z00 = fmaf(ctx0[2*u],   rs0, h0[2*u]);
                    float z01 = fmaf(ctx0[2*u+1], rs0, h0[2*u+1]);
                    float z10 = fmaf(ctx1[2*u],   rs1, h1[2*u]);
                    float z11 = fmaf(ctx1[2*u+1], rs1, h1[2*u+1]);
                    uint32_t hh, ll;
                    split2(z00, z01, hh, ll);
                    *(uint32_t*)(Ah + (lr0)     * AST + col) = hh;
                    *(uint32_t*)(Al + (lr0)     * AST + col) = ll;
                    split2(z10, z11, hh, ll);
                    *(uint32_t*)(Ah + (lr0 + 1) * AST + col) = hh;
                    *(uint32_t*)(Al + (lr0 + 1) * AST + col) = ll;
                }
            } else if (lane == NF) {
                // K-pad: bias-one at k=230, zeros 232..238 (u32 pairs)
                #pragma unroll
                for (int rr = 0; rr < 2; rr++) {
                    const int m = lr0 + rr;
                    *(uint32_t*)(Ah + m * AST + 230) = 0x00003F80u;  // (1.0bf16, 0)
                    *(uint32_t*)(Al + m * AST + 230) = 0u;
                    #pragma unroll
                    for (int col = 232; col < 240; col += 2) {
                        *(uint32_t*)(Ah + m * AST + col) = 0u;
                        *(uint32_t*)(Al + m * AST + col) = 0u;
                    }
                }
            }
            __syncwarp();
        }
    }
    __syncthreads();   // phase 1 complete; kv scratch (Bs overlay) now dead

    // cooperative async copy of one B chunk (hi+lo) into a slot
    auto issue_copy = [&](int loff, int half, int k0, int klen, int slot) {
        const unsigned char* sh = g_wb + loff + k0 * (NPB * 2);
        const unsigned char* sl = g_wb + loff + half + k0 * (NPB * 2);
        const uint32_t dst = bs_u32 + slot * (SLOT_BF * 2);
        const uint32_t dlo = dst + klen * (NPB * 2);
        const int cnt = klen * 25;
        for (int i = tid; i < cnt; i += 256) {
            CP_ASYNC16(dst + i * 16, sh + i * 16);
            CP_ASYNC16(dlo + i * 16, sl + i * 16);
        }
        CP_COMMIT();
    };

    issue_copy(wb_off(0), wb_half(0), 0, 32, 0);

    const int mg = w >> 2;            // 0..1: m-tiles {mg*2, mg*2+1}
    const int ng = w & 3;             // 0..3: n-tiles {ng*3 .. ng*3+2}

    int cur = 0;
    #pragma unroll 1
    for (int l = 0; l < 5; l++) {
        const int KP = (l == 0) ? 240 : 176;
        const int nc = (KP + 31) >> 5;
        wmma::fragment<wmma::accumulator, 16, 16, 16, float> acc[2][3];
        #pragma unroll
        for (int i = 0; i < 2; i++)
            #pragma unroll
            for (int j = 0; j < 3; j++) wmma::fill_fragment(acc[i][j], 0.f);

        #pragma unroll 1
        for (int c = 0; c < nc; c++) {
            const int k0 = c * 32;
            const int klen = (KP - k0 < 32) ? (KP - k0) : 32;
            CP_WAIT0();
            __syncthreads();
            if (c + 1 < nc) {
                const int nk0 = k0 + 32;
                issue_copy(wb_off(l), wb_half(l), nk0,
                           (KP - nk0 < 32) ? (KP - nk0) : 32, cur ^ 1);
            } else if (l < 4) {
                issue_copy(wb_off(l + 1), wb_half(l + 1), 0, 32, cur ^ 1);
            }
            const __nv_bfloat16* Bslot = Bs + cur * SLOT_BF;
            const int nks = klen >> 4;
            #pragma unroll 1
            for (int ks = 0; ks < nks; ks++) {
                wmma::fragment<wmma::matrix_a, 16, 16, 16, __nv_bfloat16, wmma::row_major> fah[2], fal[2];
                #pragma unroll
                for (int i = 0; i < 2; i++) {
                    const int mbase = (mg * 2 + i) * 16 * AST + k0 + ks * 16;
                    wmma::load_matrix_sync(fah[i], Ah + mbase, AST);
                    wmma::load_matrix_sync(fal[i], Al + mbase, AST);
                }
                #pragma unroll
                for (int j = 0; j < 3; j++) {
                    const int nbase = ks * 16 * NPB + (ng * 3 + j) * 16;
                    wmma::fragment<wmma::matrix_b, 16, 16, 16, __nv_bfloat16, wmma::row_major> fbh, fbl;
                    wmma::load_matrix_sync(fbh, Bslot + nbase, NPB);
                    wmma::load_matrix_sync(fbl, Bslot + klen * NPB + nbase, NPB);
                    #pragma unroll
                    for (int i = 0; i < 2; i++) {
                        wmma::mma_sync(acc[i][j], fah[i], fbh, acc[i][j]);
                        wmma::mma_sync(acc[i][j], fal[i], fbh, acc[i][j]);
                        wmma::mma_sync(acc[i][j], fah[i], fbl, acc[i][j]);
                    }
                }
            }
            cur ^= 1;
        }
        __syncthreads();

        // ---- epilogue: staging in the dead slot (cur^1) ----
        float* stg = (float*)(Bs + (cur ^ 1) * SLOT_BF) + w * 260;
        const int r  = lane >> 1;
        const int c0 = (lane & 1) * 8;
        if (l < 4) {
            #pragma unroll 1
            for (int i = 0; i < 2; i++) {
                #pragma unroll 1
                for (int j = 0; j < 3; j++) {
                    wmma::store_matrix_sync(stg, acc[i][j], 16, wmma::mem_row_major);
                    __syncwarp();
                    const int ncol = (ng * 3 + j) * 16 + c0;
                    float v[8];
                    #pragma unroll
                    for (int jj = 0; jj < 8; jj++) {
                        const int k = ncol + jj;
                        const float xv = stg[r * 16 + c0 + jj];
                        v[jj] = (k < 164) ? fmaxf(xv, 0.f) : ((k == 164) ? 1.f : 0.f);
                    }
                    uint32_t hh[4], ll[4];
                    #pragma unroll
                    for (int p = 0; p < 4; p++) split2(v[2*p], v[2*p+1], hh[p], ll[p]);
                    const int m = (mg * 2 + i) * 16 + r;
                    *(uint4*)(Ah + m * AST + ncol) = make_uint4(hh[0], hh[1], hh[2], hh[3]);
                    *(uint4*)(Al + m * AST + ncol) = make_uint4(ll[0], ll[1], ll[2], ll[3]);
                    __syncwarp();
                }
            }
        } else {
            float* za = (float*)smp;   // [64][168] fp32, overwrites Ah/Al
            #pragma unroll 1
            for (int i = 0; i < 2; i++) {
                #pragma unroll 1
                for (int j = 0; j < 3; j++) {
                    wmma::store_matrix_sync(stg, acc[i][j], 16, wmma::mem_row_major);
                    __syncwarp();
                    const int ncol = (ng * 3 + j) * 16 + c0;
                    const int m = (mg * 2 + i) * 16 + r;
                    #pragma unroll
                    for (int jj = 0; jj < 8; jj++) {
                        const int k = ncol + jj;
                        if (k < 164)
                            za[m * 168 + k] = fmaxf(stg[r * 16 + c0 + jj], 0.f);
                    }
                    __syncwarp();
                }
            }
        }
        __syncthreads();
    }

    // ---- heads: move[5] + mark[1], fp32 ----
    {
        float* za  = (float*)smp;
        float* whs = (float*)Bs;
        for (int i = tid; i < 1008; i += 256) {
            const int o = i / 168, k = i - o * 168;
            whs[k * 6 + o] = g_wh[i];
        }
        __syncthreads();
        if (tid < 128) {
            const int r = tid >> 1;
            const int g = tid & 1;
            const float* zr = za + r * 168;
            float a0 = g_bh[g * 3 + 0];
            float a1 = g_bh[g * 3 + 1];
            float a2 = g_bh[g * 3 + 2];
            #pragma unroll 4
            for (int k = 0; k < 164; k++) {
                const float v = zr[k];
                const float* wk = whs + k * 6 + g * 3;
                a0 = fmaf(v, wk[0], a0);
                a1 = fmaf(v, wk[1], a1);
                a2 = fmaf(v, wk[2], a2);
            }
            const int row = rowbase + r;
            if (g == 0) {
                out[row * 5 + 0] = a0;
                out[row * 5 + 1] = a1;
                out[row * 5 + 2] = a2;
            } else {
                out[row * 5 + 3] = a0;
                out[row * 5 + 4] = a1;
                out[(long long)B * 5 + row] = a2;
            }
        }
    }
}

extern "C" void kernel_launch(void* const* d_in, const int* in_sizes, int n_in,
                              void* d_out, int out_size) {
    const float* x   = (const float*)d_in[0];
    const float* Wp  = (const float*)d_in[1];
    const float* bp  = (const float*)d_in[2];
    const float* Wq  = (const float*)d_in[3];
    const float* Wk  = (const float*)d_in[4];
    const float* Wv  = (const float*)d_in[5];
    const float* W1  = (const float*)d_in[6];
    const float* b1  = (const float*)d_in[7];
    const float* W2  = (const float*)d_in[8];
    const float* b2  = (const float*)d_in[9];
    const float* W3  = (const float*)d_in[10];
    const float* b3  = (const float*)d_in[11];
    const float* W4  = (const float*)d_in[12];
    const float* b4  = (const float*)d_in[13];
    const float* W5  = (const float*)d_in[14];
    const float* b5  = (const float*)d_in[15];
    const float* Wm  = (const float*)d_in[16];
    const float* bm  = (const float*)d_in[17];
    const float* Wmk = (const float*)d_in[18];
    const float* bmk = (const float*)d_in[19];
    float* out = (float*)d_out;

    const int B = in_sizes[0] / OBS;

    cudaFuncSetAttribute(actor_fused,
                         cudaFuncAttributeMaxDynamicSharedMemorySize, SMEM2);

    pack_misc<<<dim3(232, 3), 192>>>(Wm, bm, Wmk, bmk, Wp, Wq, Wk, Wv);
    pack_wb<<<dim3(240, 10), 200>>>(W1, W2, W3, W4, W5, b1, b2, b3, b4, b5);
    actor_fused<<<B / 64, 256, SMEM2>>>(x, bp, out, B);
}

// round 17
// speedup vs baseline: 1.5190x; 1.0000x over previous
#include <cuda_runtime.h>
#include <cuda_bf16.h>
#include <mma.h>
#include <cstdint>

using namespace nvcuda;

#define FULL_MASK 0xFFFFFFFFu
typedef unsigned long long ull;

// cp.async 16B (compute_80+ PTX)
#define CP_ASYNC16(dst_u32, src_ptr) \
    asm volatile("cp.async.cg.shared.global [%0], [%1], 16;" \
                 :: "r"(dst_u32), "l"(src_ptr) : "memory")
#define CP_COMMIT() asm volatile("cp.async.commit_group;" ::: "memory")
#define CP_WAIT0()  asm volatile("cp.async.wait_group 0;" ::: "memory")

__device__ __forceinline__ uint32_t smem_u32(const void* p) {
    return (uint32_t)__cvta_generic_to_shared(p);
}

// split fp32 pair -> bf16 hi pair + bf16 lo pair (packed u32 each)
__device__ __forceinline__ void split2(float v0, float v1, uint32_t& h, uint32_t& l) {
    uint32_t hh;
    asm("cvt.rn.bf16x2.f32 %0, %1, %2;" : "=r"(hh) : "f"(v1), "f"(v0));
    const float h0 = __uint_as_float(hh << 16);
    const float h1 = __uint_as_float(hh & 0xFFFF0000u);
    uint32_t ll;
    asm("cvt.rn.bf16x2.f32 %0, %1, %2;" : "=r"(ll) : "f"(v1 - h1), "f"(v0 - h0));
    h = hh; l = ll;
}

// ---------------- model constants ----------------
__constant__ int FOFF[23] = {0,4,8,12,16,20,24,28,32,36,40,44,48,50,52,53,57,58,59,60,61,62,63};
__constant__ int FDIM[23] = {4,4,4,4,4,4,4,4,4,4,4,4, 2, 2, 1, 4, 1, 1, 1, 1, 1, 1, 2};

static constexpr int OBS  = 65;
static constexpr int NF   = 23;
static constexpr int ZDIM = 230;
static constexpr int HID  = 164;
static constexpr int NPB  = 200;   // B row stride bf16 (400 B = 16 mod 128: conflict-free)
static constexpr int AST  = 248;   // A row stride bf16 (496 B = 112 mod 128: conflict-free)
static constexpr int SLOT_BF = 12800;   // 25600 B per ping-pong slot

__device__ __align__(16) float g_wh[6 * 168];
__device__ float g_bh[6];
__device__ __align__(16) float g_wproj[NF * 10 * 4];
__device__ __align__(16) float g_wqkv[10 * 32];
__device__ int g_offadj[32];
// bf16 hi/lo weight blobs, row-major [K_pad][NPB]; bias folded at k=K_real
__device__ __align__(16) unsigned char g_wb[755200];

__host__ __device__ __forceinline__ int wb_off(int l) {
    return (l == 0) ? 0 : 192000 + (l - 1) * 140800;
}
__host__ __device__ __forceinline__ int wb_half(int l) {
    return (l == 0) ? 96000 : 70400;
}

// ======================= pack: phase1 weights + heads ===================
__global__ void pack_misc(
    const float* __restrict__ Wm, const float* __restrict__ bm,
    const float* __restrict__ Wmk, const float* __restrict__ bmk,
    const float* __restrict__ Wp,
    const float* __restrict__ Wq, const float* __restrict__ Wk,
    const float* __restrict__ Wv)
{
    const int k = blockIdx.x;
    const int l = blockIdx.y;
    const int c = threadIdx.x;
    if (l == 0) {
        if (k >= 168 || c >= 6) return;
        g_wh[c * 168 + k] = (k < HID) ? ((c < 5) ? Wm[k * 5 + c] : Wmk[k]) : 0.f;
        if (k == 0) g_bh[c] = (c < 5) ? bm[c] : bmk[0];
    } else if (l == 1) {
        if (k < ZDIM && c < 4) {
            const int i = k / 10;
            const int off  = FOFF[i];
            const int dim  = FDIM[i];
            const int offa = (off < 61) ? off : 61;
            const int shift = off - offa;
            float v = 0.f;
            if (c >= shift && (c - shift) < dim) v = Wp[(offa + c) * ZDIM + k];
            g_wproj[k * 4 + c] = v;
        }
        if (c == 4 && k < 32)
            g_offadj[k] = (k < NF) ? ((FOFF[k] < 61) ? FOFF[k] : 61) : 0;
    } else {
        if (k < 10 && c < 32) {
            float v = 0.f;
            if (c < 10)      v = Wq[k * 10 + c];
            else if (c < 20) v = Wk[k * 10 + (c - 10)];
            else if (c < 30) v = Wv[k * 10 + (c - 20)];
            g_wqkv[k * 32 + c] = v;
        }
    }
}

// ======================= pack: MLP weight blobs (bf16 hi/lo) ============
__global__ void pack_wb(
    const float* __restrict__ W1, const float* __restrict__ W2,
    const float* __restrict__ W3, const float* __restrict__ W4,
    const float* __restrict__ W5,
    const float* __restrict__ b1, const float* __restrict__ b2,
    const float* __restrict__ b3, const float* __restrict__ b4,
    const float* __restrict__ b5)
{
    const int k = blockIdx.x;
    const int l = blockIdx.y >> 1;
    const int h = blockIdx.y & 1;
    const int n = threadIdx.x;
    const int kalloc = (l == 0) ? 240 : 176;
    if (k >= kalloc) return;
    const int kreal = (l == 0) ? 230 : 164;
    const float* W = (l == 0) ? W1 : (l == 1) ? W2 : (l == 2) ? W3 : (l == 3) ? W4 : W5;
    const float* b = (l == 0) ? b1 : (l == 1) ? b2 : (l == 2) ? b3 : (l == 3) ? b4 : b5;
    float w = 0.f;
    if (n < HID) {
        if (k < kreal)       w = W[k * HID + n];
        else if (k == kreal) w = b[n];
    }
    const __nv_bfloat16 bhi = __float2bfloat16(w);
    unsigned short bits;
    if (h == 0) bits = __bfloat16_as_ushort(bhi);
    else        bits = __bfloat16_as_ushort(__float2bfloat16(w - __bfloat162float(bhi)));
    *(unsigned short*)(g_wb + wb_off(l) + h * wb_half(l) + (k * NPB + n) * 2) = bits;
}

// ======================= Fused kernel: proj+attn -> wmma MLP -> heads ===
// M=64/CTA, 256 threads, occ 2.
// smem: Ah [64][248] bf16 (31744 B) | Al (31744 B) | Bs 2 slots x 25600 B
static constexpr int AHI = 0;
static constexpr int ALO = 31744;
static constexpr int BBO = 63488;
static constexpr int SMEM2 = 63488 + 51200;   // 114688 B

__global__ void __launch_bounds__(256, 2)
actor_fused(const float* __restrict__ x, const float* __restrict__ bpj,
            float* __restrict__ out, int B)
{
    extern __shared__ char smp[];
    __nv_bfloat16* Ah = (__nv_bfloat16*)(smp + AHI);
    __nv_bfloat16* Al = (__nv_bfloat16*)(smp + ALO);
    __nv_bfloat16* Bs = (__nv_bfloat16*)(smp + BBO);
    const uint32_t bs_u32 = smem_u32(Bs);
    const int tid  = threadIdx.x;
    const int w    = tid >> 5;
    const int lane = tid & 31;
    const int rowbase = blockIdx.x * 64;

    // ================= Phase 1: proj + attention (8 rows/warp) ==========
    {
        float* kvw = (float*)(smp + BBO) + w * 1152;
        float* kb0 = kvw;
        float* vb0 = kvw + 288;
        float* kb1 = kvw + 576;
        float* vb1 = kvw + 864;

        const float inv_sqrt10 = 0.31622776601683794f;
        const int tok = (lane < NF) ? lane : 0;
        const int offa = g_offadj[tok];
        float bq[10];
        {
            const float2* b2 = (const float2*)(bpj + tok * 10);
            #pragma unroll
            for (int u = 0; u < 5; u++) { float2 t = b2[u]; bq[2*u] = t.x; bq[2*u+1] = t.y; }
        }

        #pragma unroll 1
        for (int pass = 0; pass < 4; pass++) {
            const int lr0 = w * 8 + 2 * pass;
            const int row0 = rowbase + lr0;
            const int row1 = row0 + 1;
            const float* xr0 = x + (long long)row0 * OBS + offa;
            const float* xr1 = x + (long long)row1 * OBS + offa;
            const float x00 = xr0[0], x01 = xr0[1], x02 = xr0[2], x03 = xr0[3];
            const float x10 = xr1[0], x11 = xr1[1], x12 = xr1[2], x13 = xr1[3];

            float h0[10], h1[10];
            #pragma unroll
            for (int e = 0; e < 10; e++) {
                const float4 wq = ((const float4*)g_wproj)[tok * 10 + e];
                h0[e] = fmaf(x03, wq.w, fmaf(x02, wq.z, fmaf(x01, wq.y, fmaf(x00, wq.x, bq[e]))));
                h1[e] = fmaf(x13, wq.w, fmaf(x12, wq.z, fmaf(x11, wq.y, fmaf(x10, wq.x, bq[e]))));
            }
            {
                float kk0[10], vv0[10], kk1[10], vv1[10];
                #pragma unroll
                for (int e = 0; e < 10; e++) { kk0[e]=0.f; vv0[e]=0.f; kk1[e]=0.f; vv1[e]=0.f; }
                #pragma unroll
                for (int d = 0; d < 10; d++) {
                    float wf[24];
                    #pragma unroll
                    for (int u = 0; u < 6; u++)
                        *(float4*)(wf + 4 * u) = ((const float4*)(g_wqkv + d * 32))[2 + u];
                    const float hd0 = h0[d], hd1 = h1[d];
                    #pragma unroll
                    for (int e = 0; e < 10; e++) {
                        kk0[e] = fmaf(hd0, wf[e + 2],  kk0[e]);
                        kk1[e] = fmaf(hd1, wf[e + 2],  kk1[e]);
                        vv0[e] = fmaf(hd0, wf[e + 12], vv0[e]);
                        vv1[e] = fmaf(hd1, wf[e + 12], vv1[e]);
                    }
                }
                if (lane < NF) {
                    float2* ks0 = (float2*)(kb0 + tok * 12);
                    float2* vs0 = (float2*)(vb0 + tok * 12);
                    float2* ks1 = (float2*)(kb1 + tok * 12);
                    float2* vs1 = (float2*)(vb1 + tok * 12);
                    #pragma unroll
                    for (int u = 0; u < 5; u++) {
                        ks0[u] = make_float2(kk0[2*u], kk0[2*u+1]);
                        vs0[u] = make_float2(vv0[2*u], vv0[2*u+1]);
                        ks1[u] = make_float2(kk1[2*u], kk1[2*u+1]);
                        vs1[u] = make_float2(vv1[2*u], vv1[2*u+1]);
                    }
                }
            }
            float q0[10], q1[10];
            #pragma unroll
            for (int e = 0; e < 10; e++) { q0[e] = 0.f; q1[e] = 0.f; }
            #pragma unroll
            for (int d = 0; d < 10; d++) {
                float wf[12];
                #pragma unroll
                for (int u = 0; u < 3; u++)
                    *(float4*)(wf + 4 * u) = ((const float4*)(g_wqkv + d * 32))[u];
                const float hd0 = h0[d], hd1 = h1[d];
                #pragma unroll
                for (int e = 0; e < 10; e++) {
                    q0[e] = fmaf(hd0, wf[e], q0[e]);
                    q1[e] = fmaf(hd1, wf[e], q1[e]);
                }
            }
            __syncwarp();

            float ssum0 = 0.f, ssum1 = 0.f;
            float ctx0[10], ctx1[10];
            #pragma unroll
            for (int e = 0; e < 10; e++) { ctx0[e] = 0.f; ctx1[e] = 0.f; }
            #pragma unroll 1
            for (int j = 0; j < NF; j++) {
                const float* kj0 = kb0 + j * 12;
                const float4 ka0 = *(const float4*)kj0;
                const float4 kb0v = *(const float4*)(kj0 + 4);
                const float2 kc0 = *(const float2*)(kj0 + 8);
                const float* kj1 = kb1 + j * 12;
                const float4 ka1 = *(const float4*)kj1;
                const float4 kb1v = *(const float4*)(kj1 + 4);
                const float2 kc1 = *(const float2*)(kj1 + 8);
                float dt0 = q0[0] * ka0.x;
                float dt1 = q1[0] * ka1.x;
                dt0 = fmaf(q0[1], ka0.y, dt0);  dt1 = fmaf(q1[1], ka1.y, dt1);
                dt0 = fmaf(q0[2], ka0.z, dt0);  dt1 = fmaf(q1[2], ka1.z, dt1);
                dt0 = fmaf(q0[3], ka0.w, dt0);  dt1 = fmaf(q1[3], ka1.w, dt1);
                dt0 = fmaf(q0[4], kb0v.x, dt0); dt1 = fmaf(q1[4], kb1v.x, dt1);
                dt0 = fmaf(q0[5], kb0v.y, dt0); dt1 = fmaf(q1[5], kb1v.y, dt1);
                dt0 = fmaf(q0[6], kb0v.z, dt0); dt1 = fmaf(q1[6], kb1v.z, dt1);
                dt0 = fmaf(q0[7], kb0v.w, dt0); dt1 = fmaf(q1[7], kb1v.w, dt1);
                dt0 = fmaf(q0[8], kc0.x, dt0);  dt1 = fmaf(q1[8], kc1.x, dt1);
                dt0 = fmaf(q0[9], kc0.y, dt0);  dt1 = fmaf(q1[9], kc1.y, dt1);
                const float pe0 = __expf(dt0 * inv_sqrt10);
                const float pe1 = __expf(dt1 * inv_sqrt10);
                ssum0 += pe0;
                ssum1 += pe1;
                const float* vj0 = vb0 + j * 12;
                const float4 va0 = *(const float4*)vj0;
                const float4 vb0v = *(const float4*)(vj0 + 4);
                const float2 vc0 = *(const float2*)(vj0 + 8);
                const float* vj1 = vb1 + j * 12;
                const float4 va1 = *(const float4*)vj1;
                const float4 vb1v = *(const float4*)(vj1 + 4);
                const float2 vc1 = *(const float2*)(vj1 + 8);
                ctx0[0] = fmaf(pe0, va0.x, ctx0[0]);  ctx1[0] = fmaf(pe1, va1.x, ctx1[0]);
                ctx0[1] = fmaf(pe0, va0.y, ctx0[1]);  ctx1[1] = fmaf(pe1, va1.y, ctx1[1]);
                ctx0[2] = fmaf(pe0, va0.z, ctx0[2]);  ctx1[2] = fmaf(pe1, va1.z, ctx1[2]);
                ctx0[3] = fmaf(pe0, va0.w, ctx0[3]);  ctx1[3] = fmaf(pe1, va1.w, ctx1[3]);
                ctx0[4] = fmaf(pe0, vb0v.x, ctx0[4]); ctx1[4] = fmaf(pe1, vb1v.x, ctx1[4]);
                ctx0[5] = fmaf(pe0, vb0v.y, ctx0[5]); ctx1[5] = fmaf(pe1, vb1v.y, ctx1[5]);
                ctx0[6] = fmaf(pe0, vb0v.z, ctx0[6]); ctx1[6] = fmaf(pe1, vb1v.z, ctx1[6]);
                ctx0[7] = fmaf(pe0, vb0v.w, ctx0[7]); ctx1[7] = fmaf(pe1, vb1v.w, ctx1[7]);
                ctx0[8] = fmaf(pe0, vc0.x, ctx0[8]);  ctx1[8] = fmaf(pe1, vc1.x, ctx1[8]);
                ctx0[9] = fmaf(pe0, vc0.y, ctx0[9]);  ctx1[9] = fmaf(pe1, vc1.y, ctx1[9]);
            }
            const float rs0 = __fdividef(1.f, ssum0);
            const float rs1 = __fdividef(1.f, ssum1);
            if (lane < NF) {
                #pragma unroll
                for (int u = 0; u < 5; u++) {
                    const int col = tok * 10 + 2 * u;
                    float z00 = fmaf(ctx0[2*u],   rs0, h0[2*u]);
                    float z01 = fmaf(ctx0[2*u+1], rs0, h0[2*u+1]);
                    float z10 = fmaf(ctx1[2*u],   rs1, h1[2*u]);
                    float z11 = fmaf(ctx1[2*u+1], rs1, h1[2*u+1]);
                    uint32_t hh, ll;
                    split2(z00, z01, hh, ll);
                    *(uint32_t*)(Ah + (lr0)     * AST + col) = hh;
                    *(uint32_t*)(Al + (lr0)     * AST + col) = ll;
                    split2(z10, z11, hh, ll);
                    *(uint32_t*)(Ah + (lr0 + 1) * AST + col) = hh;
                    *(uint32_t*)(Al + (lr0 + 1) * AST + col) = ll;
                }
            } else if (lane == NF) {
                #pragma unroll
                for (int rr = 0; rr < 2; rr++) {
                    const int m = lr0 + rr;
                    *(uint32_t*)(Ah + m * AST + 230) = 0x00003F80u;
                    *(uint32_t*)(Al + m * AST + 230) = 0u;
                    #pragma unroll
                    for (int col = 232; col < 240; col += 2) {
                        *(uint32_t*)(Ah + m * AST + col) = 0u;
                        *(uint32_t*)(Al + m * AST + col) = 0u;
                    }
                }
            }
            __syncwarp();
        }
    }
    __syncthreads();

    auto issue_copy = [&](int loff, int half, int k0, int klen, int slot) {
        const unsigned char* sh = g_wb + loff + k0 * (NPB * 2);
        const unsigned char* sl = g_wb + loff + half + k0 * (NPB * 2);
        const uint32_t dst = bs_u32 + slot * (SLOT_BF * 2);
        const uint32_t dlo = dst + klen * (NPB * 2);
        const int cnt = klen * 25;
        for (int i = tid; i < cnt; i += 256) {
            CP_ASYNC16(dst + i * 16, sh + i * 16);
            CP_ASYNC16(dlo + i * 16, sl + i * 16);
        }
        CP_COMMIT();
    };

    issue_copy(wb_off(0), wb_half(0), 0, 32, 0);

    const int mg = w >> 2;
    const int ng = w & 3;

    int cur = 0;
    #pragma unroll 1
    for (int l = 0; l < 5; l++) {
        const int KP = (l == 0) ? 240 : 176;
        const int nc = (KP + 31) >> 5;
        wmma::fragment<wmma::accumulator, 16, 16, 16, float> acc[2][3];
        #pragma unroll
        for (int i = 0; i < 2; i++)
            #pragma unroll
            for (int j = 0; j < 3; j++) wmma::fill_fragment(acc[i][j], 0.f);

        #pragma unroll 1
        for (int c = 0; c < nc; c++) {
            const int k0 = c * 32;
            const int klen = (KP - k0 < 32) ? (KP - k0) : 32;
            CP_WAIT0();
            __syncthreads();
            if (c + 1 < nc) {
                const int nk0 = k0 + 32;
                issue_copy(wb_off(l), wb_half(l), nk0,
                           (KP - nk0 < 32) ? (KP - nk0) : 32, cur ^ 1);
            } else if (l < 4) {
                issue_copy(wb_off(l + 1), wb_half(l + 1), 0, 32, cur ^ 1);
            }
            const __nv_bfloat16* Bslot = Bs + cur * SLOT_BF;
            const int nks = klen >> 4;
            #pragma unroll 1
            for (int ks = 0; ks < nks; ks++) {
                wmma::fragment<wmma::matrix_a, 16, 16, 16, __nv_bfloat16, wmma::row_major> fah[2], fal[2];
                wmma::fragment<wmma::matrix_b, 16, 16, 16, __nv_bfloat16, wmma::row_major> fbh[3], fbl[3];
                #pragma unroll
                for (int i = 0; i < 2; i++) {
                    const int mbase = (mg * 2 + i) * 16 * AST + k0 + ks * 16;
                    wmma::load_matrix_sync(fah[i], Ah + mbase, AST);
                    wmma::load_matrix_sync(fal[i], Al + mbase, AST);
                }
                #pragma unroll
                for (int j = 0; j < 3; j++) {
                    const int nbase = ks * 16 * NPB + (ng * 3 + j) * 16;
                    wmma::load_matrix_sync(fbh[j], Bslot + nbase, NPB);
                    wmma::load_matrix_sync(fbl[j], Bslot + klen * NPB + nbase, NPB);
                }
                // term-major issue: each acc's dependent MMAs are separated
                // by 5 independent ones -> HMMA latency fully covered.
                #pragma unroll
                for (int j = 0; j < 3; j++)
                    #pragma unroll
                    for (int i = 0; i < 2; i++)
                        wmma::mma_sync(acc[i][j], fah[i], fbh[j], acc[i][j]);
                #pragma unroll
                for (int j = 0; j < 3; j++)
                    #pragma unroll
                    for (int i = 0; i < 2; i++)
                        wmma::mma_sync(acc[i][j], fal[i], fbh[j], acc[i][j]);
                #pragma unroll
                for (int j = 0; j < 3; j++)
                    #pragma unroll
                    for (int i = 0; i < 2; i++)
                        wmma::mma_sync(acc[i][j], fah[i], fbl[j], acc[i][j]);
            }
            cur ^= 1;
        }
        __syncthreads();

        // ---- epilogue: staging in the dead slot (cur^1) ----
        float* stg = (float*)(Bs + (cur ^ 1) * SLOT_BF) + w * 260;
        const int r  = lane >> 1;
        const int c0 = (lane & 1) * 8;
        if (l < 4) {
            #pragma unroll 1
            for (int i = 0; i < 2; i++) {
                #pragma unroll 1
                for (int j = 0; j < 3; j++) {
                    wmma::store_matrix_sync(stg, acc[i][j], 16, wmma::mem_row_major);
                    __syncwarp();
                    const int ncol = (ng * 3 + j) * 16 + c0;
                    float v[8];
                    #pragma unroll
                    for (int jj = 0; jj < 8; jj++) {
                        const int k = ncol + jj;
                        const float xv = stg[r * 16 + c0 + jj];
                        v[jj] = (k < 164) ? fmaxf(xv, 0.f) : ((k == 164) ? 1.f : 0.f);
                    }
                    uint32_t hh[4], ll[4];
                    #pragma unroll
                    for (int p = 0; p < 4; p++) split2(v[2*p], v[2*p+1], hh[p], ll[p]);
                    const int m = (mg * 2 + i) * 16 + r;
                    *(uint4*)(Ah + m * AST + ncol) = make_uint4(hh[0], hh[1], hh[2], hh[3]);
                    *(uint4*)(Al + m * AST + ncol) = make_uint4(ll[0], ll[1], ll[2], ll[3]);
                    __syncwarp();
                }
            }
        } else {
            float* za = (float*)smp;
            #pragma unroll 1
            for (int i = 0; i < 2; i++) {
                #pragma unroll 1
                for (int j = 0; j < 3; j++) {
                    wmma::store_matrix_sync(stg, acc[i][j], 16, wmma::mem_row_major);
                    __syncwarp();
                    const int ncol = (ng * 3 + j) * 16 + c0;
                    const int m = (mg * 2 + i) * 16 + r;
                    #pragma unroll
                    for (int jj = 0; jj < 8; jj++) {
                        const int k = ncol + jj;
                        if (k < 164)
                            za[m * 168 + k] = fmaxf(stg[r * 16 + c0 + jj], 0.f);
                    }
                    __syncwarp();
                }
            }
        }
        __syncthreads();
    }

    // ---- heads: move[5] + mark[1], fp32 ----
    {
        float* za  = (float*)smp;
        float* whs = (float*)Bs;
        for (int i = tid; i < 1008; i += 256) {
            const int o = i / 168, k = i - o * 168;
            whs[k * 6 + o] = g_wh[i];
        }
        __syncthreads();
        if (tid < 128) {
            const int r = tid >> 1;
            const int g = tid & 1;
            const float* zr = za + r * 168;
            float a0 = g_bh[g * 3 + 0];
            float a1 = g_bh[g * 3 + 1];
            float a2 = g_bh[g * 3 + 2];
            #pragma unroll 4
            for (int k = 0; k < 164; k++) {
                const float v = zr[k];
                const float* wk = whs + k * 6 + g * 3;
                a0 = fmaf(v, wk[0], a0);
                a1 = fmaf(v, wk[1], a1);
                a2 = fmaf(v, wk[2], a2);
            }
            const int row = rowbase + r;
            if (g == 0) {
                out[row * 5 + 0] = a0;
                out[row * 5 + 1] = a1;
                out[row * 5 + 2] = a2;
            } else {
                out[row * 5 + 3] = a0;
                out[row * 5 + 4] = a1;
                out[(long long)B * 5 + row] = a2;
            }
        }
    }
}

extern "C" void kernel_launch(void* const* d_in, const int* in_sizes, int n_in,
                              void* d_out, int out_size) {
    const float* x   = (const float*)d_in[0];
    const float* Wp  = (const float*)d_in[1];
    const float* bp  = (const float*)d_in[2];
    const float* Wq  = (const float*)d_in[3];
    const float* Wk  = (const float*)d_in[4];
    const float* Wv  = (const float*)d_in[5];
    const float* W1  = (const float*)d_in[6];
    const float* b1  = (const float*)d_in[7];
    const float* W2  = (const float*)d_in[8];
    const float* b2  = (const float*)d_in[9];
    const float* W3  = (const float*)d_in[10];
    const float* b3  = (const float*)d_in[11];
    const float* W4  = (const float*)d_in[12];
    const float* b4  = (const float*)d_in[13];
    const float* W5  = (const float*)d_in[14];
    const float* b5  = (const float*)d_in[15];
    const float* Wm  = (const float*)d_in[16];
    const float* bm  = (const float*)d_in[17];
    const float* Wmk = (const float*)d_in[18];
    const float* bmk = (const float*)d_in[19];
    float* out = (float*)d_out;

    const int B = in_sizes[0] / OBS;

    cudaFuncSetAttribute(actor_fused,
                         cudaFuncAttributeMaxDynamicSharedMemorySize, SMEM2);

    pack_misc<<<dim3(232, 3), 192>>>(Wm, bm, Wmk, bmk, Wp, Wq, Wk, Wv);
    pack_wb<<<dim3(240, 10), 200>>>(W1, W2, W3, W4, W5, b1, b2, b3, b4, b5);
    actor_fused<<<B / 64, 256, SMEM2>>>(x, bp, out, B);
}